// round 2
// baseline (speedup 1.0000x reference)
#include <cuda_runtime.h>
#include <cuda_bf16.h>
#include <math.h>
#include <stdint.h>

#define VOCAB 50257
#define DHID  128
#define NTOK  1024
#define NFREQ 256
#define SEQ   512
#define KPAD  136              // bf16 per smem row (stride 272B -> conflict-free frags)
#define NTILES 786             // ceil(50257/64)
#define NCHUNK 42
#define NBLK   19              // ceil(786/42)
#define GEMM_SMEM (4*128*KPAD*2 + 4*64*KPAD*2)  // 208896 bytes

// ---------------- device scratch ----------------
__device__ __align__(16) float g_xr[NTOK*DHID];
__device__ __align__(16) float g_xi[NTOK*DHID];
__device__ __align__(16) float g_xc[NTOK*DHID];
__device__ __align__(16) float g_cs[NTOK*NFREQ];
__device__ __align__(16) float g_ss[NTOK*NFREQ];
__device__ __align__(16) __nv_bfloat16 g_WrH[VOCAB*DHID];
__device__ __align__(16) __nv_bfloat16 g_WrL[VOCAB*DHID];
__device__ __align__(16) __nv_bfloat16 g_WiH[VOCAB*DHID];
__device__ __align__(16) __nv_bfloat16 g_WiL[VOCAB*DHID];
__device__ __align__(16) __nv_bfloat16 g_ArH[NTOK*DHID];
__device__ __align__(16) __nv_bfloat16 g_ArL[NTOK*DHID];
__device__ __align__(16) __nv_bfloat16 g_AiH[NTOK*DHID];
__device__ __align__(16) __nv_bfloat16 g_AiL[NTOK*DHID];

// ---------------- small kernels ----------------
__global__ void embed_kernel(const int* __restrict__ ids, const float* __restrict__ emb) {
    int t = blockIdx.x, d = threadIdx.x;
    int id = ids[t];
    g_xr[t*DHID + d] = emb[(size_t)id*256 + d];
    g_xi[t*DHID + d] = emb[(size_t)id*256 + 128 + d];
}

__global__ void wsplit_kernel(const float* __restrict__ Wr, const float* __restrict__ Wi) {
    int i = blockIdx.x*256 + threadIdx.x;
    if (i < VOCAB*DHID) {
        float a = Wr[i];
        __nv_bfloat16 h = __float2bfloat16(a);
        g_WrH[i] = h; g_WrL[i] = __float2bfloat16(a - __bfloat162float(h));
        float b = Wi[i];
        __nv_bfloat16 h2 = __float2bfloat16(b);
        g_WiH[i] = h2; g_WiL[i] = __float2bfloat16(b - __bfloat162float(h2));
    }
}

__global__ void asplit_kernel() {
    int i = blockIdx.x*256 + threadIdx.x;
    float r = g_xr[i];
    __nv_bfloat16 h = __float2bfloat16(r);
    g_ArH[i] = h; g_ArL[i] = __float2bfloat16(r - __bfloat162float(h));
    float q = g_xi[i];
    __nv_bfloat16 h2 = __float2bfloat16(q);
    g_AiH[i] = h2; g_AiL[i] = __float2bfloat16(q - __bfloat162float(h2));
}

// xc[t][d] = sum_k [xr|xi][t][k] * cw[d][k] + cb[d]   (K=256)
__global__ void xc_kernel(const float* __restrict__ cwl, const float* __restrict__ cbl) {
    __shared__ __align__(16) float xs[8*256];
    int tid = threadIdx.x, tBase = blockIdx.x*8;
    for (int i = tid; i < 8*256; i += 128) {
        int t = i >> 8, k = i & 255;
        xs[i] = (k < 128) ? g_xr[(tBase+t)*DHID + k] : g_xi[(tBase+t)*DHID + k - 128];
    }
    __syncthreads();
    int d = tid;
    float cb = cbl[d], acc[8];
    #pragma unroll
    for (int t = 0; t < 8; t++) acc[t] = cb;
    for (int k = 0; k < 256; k += 4) {
        float4 w = *reinterpret_cast<const float4*>(&cwl[d*256 + k]);
        #pragma unroll
        for (int t = 0; t < 8; t++) {
            acc[t] = fmaf(w.x, xs[t*256+k+0], acc[t]);
            acc[t] = fmaf(w.y, xs[t*256+k+1], acc[t]);
            acc[t] = fmaf(w.z, xs[t*256+k+2], acc[t]);
            acc[t] = fmaf(w.w, xs[t*256+k+3], acc[t]);
        }
    }
    #pragma unroll
    for (int t = 0; t < 8; t++) g_xc[(tBase+t)*DHID + d] = acc[t];
}

// cos_sum/sin_sum for one layer (reduce over d=128 within a warp, 4 d per lane)
__global__ void theta_kernel(const float* __restrict__ Wl, const float* __restrict__ Bpl,
                             const float* __restrict__ acl, const float* __restrict__ asl) {
    __shared__ __align__(16) float xs[16*128];
    const float KSCALE = (float)(4096.0 / 6.283185307179586);
    const float ASTEP  = (float)(6.283185307179586 / 4096.0);
    const float PHI_F  = 1.6180339887498948f;
    int tid = threadIdx.x, warp = tid >> 5, lane = tid & 31;
    int n = blockIdx.x*4 + warp;
    int tBase = blockIdx.y*16;
    for (int i = tid; i < 16*128; i += 128)
        xs[i] = g_xc[(tBase + (i >> 7))*DHID + (i & 127)];
    __syncthreads();
    int d0 = lane*4;
    float4 w4  = *reinterpret_cast<const float4*>(&Wl [n*DHID + d0]);
    float4 bp4 = *reinterpret_cast<const float4*>(&Bpl[n*DHID + d0]);
    float4 ac4 = *reinterpret_cast<const float4*>(&acl[n*DHID + d0]);
    float4 as4 = *reinterpret_cast<const float4*>(&asl[n*DHID + d0]);
    float4 rw;
    rw.x = 1.0f/(1.0f+fabsf(w4.x)); rw.y = 1.0f/(1.0f+fabsf(w4.y));
    rw.z = 1.0f/(1.0f+fabsf(w4.z)); rw.w = 1.0f/(1.0f+fabsf(w4.w));
    for (int tt = 0; tt < 16; tt++) {
        int tok = tBase + tt;
        float tpos = (float)(tok & (SEQ-1)) * PHI_F;
        float4 x4 = *reinterpret_cast<const float4*>(&xs[tt*128 + d0]);
        float cs = 0.f, ss = 0.f, sv, cv, th; int idx;
        th = fmaf(x4.x, rw.x, bp4.x) + tpos;
        idx = __float2int_rd(th * KSCALE) & 4095;
        __sincosf((float)idx * ASTEP, &sv, &cv);
        cs = fmaf(cv, ac4.x, cs); ss = fmaf(sv, as4.x, ss);
        th = fmaf(x4.y, rw.y, bp4.y) + tpos;
        idx = __float2int_rd(th * KSCALE) & 4095;
        __sincosf((float)idx * ASTEP, &sv, &cv);
        cs = fmaf(cv, ac4.y, cs); ss = fmaf(sv, as4.y, ss);
        th = fmaf(x4.z, rw.z, bp4.z) + tpos;
        idx = __float2int_rd(th * KSCALE) & 4095;
        __sincosf((float)idx * ASTEP, &sv, &cv);
        cs = fmaf(cv, ac4.z, cs); ss = fmaf(sv, as4.z, ss);
        th = fmaf(x4.w, rw.w, bp4.w) + tpos;
        idx = __float2int_rd(th * KSCALE) & 4095;
        __sincosf((float)idx * ASTEP, &sv, &cv);
        cs = fmaf(cv, ac4.w, cs); ss = fmaf(sv, as4.w, ss);
        #pragma unroll
        for (int off = 16; off > 0; off >>= 1) {
            cs += __shfl_down_sync(0xffffffffu, cs, off);
            ss += __shfl_down_sync(0xffffffffu, ss, off);
        }
        if (lane == 0) { g_cs[tok*NFREQ + n] = cs; g_ss[tok*NFREQ + n] = ss; }
    }
}

// xr/xi = silu(cs @ opr^T), silu(ss @ opi^T)   (K=256)
__global__ void op_kernel(const float* __restrict__ oprl, const float* __restrict__ opil) {
    __shared__ __align__(16) float cs_s[8*256];
    __shared__ __align__(16) float ss_s[8*256];
    int tid = threadIdx.x, tBase = blockIdx.x*8;
    for (int i = tid; i < 8*256; i += 128) {
        int t = i >> 8, k = i & 255;
        cs_s[i] = g_cs[(tBase+t)*NFREQ + k];
        ss_s[i] = g_ss[(tBase+t)*NFREQ + k];
    }
    __syncthreads();
    int d = tid;
    float accr[8], acci[8];
    #pragma unroll
    for (int t = 0; t < 8; t++) { accr[t] = 0.f; acci[t] = 0.f; }
    for (int k = 0; k < 256; k += 4) {
        float4 wr = *reinterpret_cast<const float4*>(&oprl[d*256 + k]);
        float4 wi = *reinterpret_cast<const float4*>(&opil[d*256 + k]);
        #pragma unroll
        for (int t = 0; t < 8; t++) {
            accr[t] = fmaf(wr.x, cs_s[t*256+k+0], accr[t]);
            accr[t] = fmaf(wr.y, cs_s[t*256+k+1], accr[t]);
            accr[t] = fmaf(wr.z, cs_s[t*256+k+2], accr[t]);
            accr[t] = fmaf(wr.w, cs_s[t*256+k+3], accr[t]);
            acci[t] = fmaf(wi.x, ss_s[t*256+k+0], acci[t]);
            acci[t] = fmaf(wi.y, ss_s[t*256+k+1], acci[t]);
            acci[t] = fmaf(wi.z, ss_s[t*256+k+2], acci[t]);
            acci[t] = fmaf(wi.w, ss_s[t*256+k+3], acci[t]);
        }
    }
    #pragma unroll
    for (int t = 0; t < 8; t++) {
        float vr = accr[t], vi = acci[t];
        g_xr[(tBase+t)*DHID + d] = vr / (1.0f + expf(-vr));
        g_xi[(tBase+t)*DHID + d] = vi / (1.0f + expf(-vi));
    }
}

// ---------------- vocab GEMM: bf16x3 split on mma.sync m16n8k16 ----------------
__device__ __forceinline__ void mma_bf16(float c[4], const uint32_t a[4], const uint32_t b[2]) {
    asm volatile(
        "mma.sync.aligned.m16n8k16.row.col.f32.bf16.bf16.f32 "
        "{%0,%1,%2,%3}, {%4,%5,%6,%7}, {%8,%9}, {%0,%1,%2,%3};\n"
        : "+f"(c[0]), "+f"(c[1]), "+f"(c[2]), "+f"(c[3])
        : "r"(a[0]), "r"(a[1]), "r"(a[2]), "r"(a[3]), "r"(b[0]), "r"(b[1]));
}

__global__ void __launch_bounds__(256) gemm_kernel(float* __restrict__ out) {
    extern __shared__ __align__(16) char sm[];
    char* sA[4]; char* sB[4];
    sA[0] = sm;                     // ArH
    sA[1] = sA[0] + 128*KPAD*2;     // ArL
    sA[2] = sA[1] + 128*KPAD*2;     // AiH
    sA[3] = sA[2] + 128*KPAD*2;     // AiL
    sB[0] = sA[3] + 128*KPAD*2;     // WrH
    sB[1] = sB[0] + 64*KPAD*2;      // WrL
    sB[2] = sB[1] + 64*KPAD*2;      // WiH
    sB[3] = sB[2] + 64*KPAD*2;      // WiL

    const int tid = threadIdx.x;
    const int mBase = blockIdx.y * 128;

    // load A tiles once
    {
        const uint4* srcA[4] = { (const uint4*)g_ArH, (const uint4*)g_ArL,
                                 (const uint4*)g_AiH, (const uint4*)g_AiL };
        #pragma unroll
        for (int mtx = 0; mtx < 4; mtx++) {
            const uint4* src = srcA[mtx] + mBase*16;
            for (int i = tid; i < 128*16; i += 256) {
                int r = i >> 4, c = i & 15;
                *reinterpret_cast<uint4*>(sA[mtx] + r*(KPAD*2) + c*16) = src[r*16 + c];
            }
        }
    }

    const int warp = tid >> 5, lane = tid & 31;
    const int wm = warp >> 1, wn = warp & 1;
    const int g = lane >> 2, tg = lane & 3;

    // per-thread smem byte offsets
    int aRow0 = (wm*32 + g) * (KPAD*2) + tg*4;       // mf adds 16*(KPAD*2), +8 row adds 8*(KPAD*2)
    int bRow0 = (wn*32 + g) * (KPAD*2) + tg*4;       // nf adds 8*(KPAD*2)
    const int rowStep8 = 8*(KPAD*2);

    int ntStart = blockIdx.x * NCHUNK;
    int ntEnd   = ntStart + NCHUNK; if (ntEnd > NTILES) ntEnd = NTILES;

    for (int nt = ntStart; nt < ntEnd; ++nt) {
        int nBase = nt * 64;
        __syncthreads();
        // load B tile (guarded)
        {
            const uint4* srcB[4] = { (const uint4*)g_WrH, (const uint4*)g_WrL,
                                     (const uint4*)g_WiH, (const uint4*)g_WiL };
            const uint4 z = {0u,0u,0u,0u};
            #pragma unroll
            for (int mtx = 0; mtx < 4; mtx++) {
                const uint4* src = srcB[mtx];
                for (int i = tid; i < 64*16; i += 256) {
                    int r = i >> 4, c = i & 15;
                    int v = nBase + r;
                    uint4 val = (v < VOCAB) ? src[(size_t)v*16 + c] : z;
                    *reinterpret_cast<uint4*>(sB[mtx] + r*(KPAD*2) + c*16) = val;
                }
            }
        }
        __syncthreads();

        float accr[2][4][4], acci[2][4][4];
        #pragma unroll
        for (int mf = 0; mf < 2; mf++)
            #pragma unroll
            for (int nf = 0; nf < 4; nf++)
                #pragma unroll
                for (int q = 0; q < 4; q++) { accr[mf][nf][q] = 0.f; acci[mf][nf][q] = 0.f; }

        #pragma unroll 1
        for (int ks = 0; ks < 8; ks++) {
            int kb = ks*32;  // byte offset of k-step (16 bf16)
            uint32_t B[4][4][2];
            #pragma unroll
            for (int mtx = 0; mtx < 4; mtx++)
                #pragma unroll
                for (int nf = 0; nf < 4; nf++) {
                    int base = bRow0 + nf*rowStep8 + kb;
                    B[mtx][nf][0] = *(const uint32_t*)(sB[mtx] + base);
                    B[mtx][nf][1] = *(const uint32_t*)(sB[mtx] + base + 16);
                }
            uint32_t Ah[2][4], Al[2][4];
            // --- Ar ---
            #pragma unroll
            for (int mf = 0; mf < 2; mf++) {
                int base = aRow0 + mf*(16*KPAD*2) + kb;
                Ah[mf][0] = *(const uint32_t*)(sA[0] + base);
                Ah[mf][1] = *(const uint32_t*)(sA[0] + base + rowStep8);
                Ah[mf][2] = *(const uint32_t*)(sA[0] + base + 16);
                Ah[mf][3] = *(const uint32_t*)(sA[0] + base + rowStep8 + 16);
                Al[mf][0] = *(const uint32_t*)(sA[1] + base);
                Al[mf][1] = *(const uint32_t*)(sA[1] + base + rowStep8);
                Al[mf][2] = *(const uint32_t*)(sA[1] + base + 16);
                Al[mf][3] = *(const uint32_t*)(sA[1] + base + rowStep8 + 16);
            }
            #pragma unroll
            for (int mf = 0; mf < 2; mf++)
                #pragma unroll
                for (int nf = 0; nf < 4; nf++) {
                    mma_bf16(accr[mf][nf], Ah[mf], B[0][nf]);  // ArH*WrH
                    mma_bf16(accr[mf][nf], Ah[mf], B[1][nf]);  // ArH*WrL
                    mma_bf16(accr[mf][nf], Al[mf], B[0][nf]);  // ArL*WrH
                    mma_bf16(acci[mf][nf], Ah[mf], B[2][nf]);  // ArH*WiH
                    mma_bf16(acci[mf][nf], Ah[mf], B[3][nf]);  // ArH*WiL
                    mma_bf16(acci[mf][nf], Al[mf], B[2][nf]);  // ArL*WiH
                }
            // --- Ai ---
            #pragma unroll
            for (int mf = 0; mf < 2; mf++) {
                int base = aRow0 + mf*(16*KPAD*2) + kb;
                Ah[mf][0] = *(const uint32_t*)(sA[2] + base);
                Ah[mf][1] = *(const uint32_t*)(sA[2] + base + rowStep8);
                Ah[mf][2] = *(const uint32_t*)(sA[2] + base + 16);
                Ah[mf][3] = *(const uint32_t*)(sA[2] + base + rowStep8 + 16);
                Al[mf][0] = *(const uint32_t*)(sA[3] + base);
                Al[mf][1] = *(const uint32_t*)(sA[3] + base + rowStep8);
                Al[mf][2] = *(const uint32_t*)(sA[3] + base + 16);
                Al[mf][3] = *(const uint32_t*)(sA[3] + base + rowStep8 + 16);
            }
            #pragma unroll
            for (int mf = 0; mf < 2; mf++)
                #pragma unroll
                for (int nf = 0; nf < 4; nf++) {
                    mma_bf16(acci[mf][nf], Ah[mf], B[0][nf]);  // AiH*WrH
                    mma_bf16(acci[mf][nf], Ah[mf], B[1][nf]);  // AiH*WrL
                    mma_bf16(acci[mf][nf], Al[mf], B[0][nf]);  // AiL*WrH
                }
            // negate Ai (packed bf16x2 sign flip) then accumulate -xi*Wi into lr
            #pragma unroll
            for (int mf = 0; mf < 2; mf++)
                #pragma unroll
                for (int q = 0; q < 4; q++) {
                    Ah[mf][q] ^= 0x80008000u; Al[mf][q] ^= 0x80008000u;
                }
            #pragma unroll
            for (int mf = 0; mf < 2; mf++)
                #pragma unroll
                for (int nf = 0; nf < 4; nf++) {
                    mma_bf16(accr[mf][nf], Ah[mf], B[2][nf]);  // -AiH*WiH
                    mma_bf16(accr[mf][nf], Ah[mf], B[3][nf]);  // -AiH*WiL
                    mma_bf16(accr[mf][nf], Al[mf], B[2][nf]);  // -AiL*WiH
                }
        }

        // epilogue: out = sqrt(lr^2 + li^2 + 1e-8)
        #pragma unroll
        for (int mf = 0; mf < 2; mf++) {
            int r0 = mBase + wm*32 + mf*16 + g;
            #pragma unroll
            for (int nf = 0; nf < 4; nf++) {
                int c0 = nBase + wn*32 + nf*8 + 2*tg;
                float* o0 = out + (size_t)r0*VOCAB;
                float* o1 = o0 + (size_t)8*VOCAB;
                if (c0 < VOCAB) {
                    float lr = accr[mf][nf][0], li = acci[mf][nf][0];
                    o0[c0] = sqrtf(fmaf(lr,lr,fmaf(li,li,1e-8f)));
                    lr = accr[mf][nf][2]; li = acci[mf][nf][2];
                    o1[c0] = sqrtf(fmaf(lr,lr,fmaf(li,li,1e-8f)));
                }
                if (c0 + 1 < VOCAB) {
                    float lr = accr[mf][nf][1], li = acci[mf][nf][1];
                    o0[c0+1] = sqrtf(fmaf(lr,lr,fmaf(li,li,1e-8f)));
                    lr = accr[mf][nf][3]; li = acci[mf][nf][3];
                    o1[c0+1] = sqrtf(fmaf(lr,lr,fmaf(li,li,1e-8f)));
                }
            }
        }
    }
}

// ---------------- launch ----------------
extern "C" void kernel_launch(void* const* d_in, const int* in_sizes, int n_in,
                              void* d_out, int out_size) {
    const int*   ids  = (const int*)  d_in[0];
    const float* emb  = (const float*)d_in[1];
    const float* cw   = (const float*)d_in[2];
    const float* cb   = (const float*)d_in[3];
    const float* W    = (const float*)d_in[4];
    const float* Bp   = (const float*)d_in[5];
    const float* acos_= (const float*)d_in[6];
    const float* asin_= (const float*)d_in[7];
    const float* opr  = (const float*)d_in[8];
    const float* opi  = (const float*)d_in[9];
    const float* Wr   = (const float*)d_in[10];
    const float* Wi   = (const float*)d_in[11];
    float* out = (float*)d_out;

    cudaFuncSetAttribute(gemm_kernel, cudaFuncAttributeMaxDynamicSharedMemorySize, GEMM_SMEM);

    embed_kernel<<<NTOK, 128>>>(ids, emb);
    wsplit_kernel<<<(VOCAB*DHID + 255)/256, 256>>>(Wr, Wi);

    for (int l = 0; l < 2; l++) {
        xc_kernel<<<NTOK/8, 128>>>(cw + (size_t)l*DHID*2*DHID, cb + (size_t)l*DHID);
        dim3 tg(NFREQ/4, NTOK/16);
        theta_kernel<<<tg, 128>>>(W + (size_t)l*NFREQ*DHID, Bp + (size_t)l*NFREQ*DHID,
                                  acos_ + (size_t)l*NFREQ*DHID, asin_ + (size_t)l*NFREQ*DHID);
        op_kernel<<<NTOK/8, 128>>>(opr + (size_t)l*DHID*NFREQ, opi + (size_t)l*DHID*NFREQ);
    }

    asplit_kernel<<<NTOK*DHID/256, 256>>>();
    gemm_kernel<<<dim3(NBLK, 8), 256, GEMM_SMEM>>>(out);
}

// round 5
// speedup vs baseline: 1.3959x; 1.3959x over previous
#include <cuda_runtime.h>
#include <cuda_fp16.h>
#include <math.h>
#include <stdint.h>

#define VOCAB 50257
#define DHID  128
#define NTOK  1024
#define NFREQ 256
#define SEQ   512

// ---------------- device scratch ----------------
__device__ __align__(16) float g_xr[NTOK*DHID];
__device__ __align__(16) float g_xi[NTOK*DHID];
__device__ __align__(16) float g_xc[NTOK*DHID];
__device__ __align__(16) float g_cs[NTOK*NFREQ];
__device__ __align__(16) float g_ss[NTOK*NFREQ];
__device__ __align__(16) __half g_WrH[VOCAB*DHID];
__device__ __align__(16) __half g_WrL[VOCAB*DHID];
__device__ __align__(16) __half g_WiH[VOCAB*DHID];
__device__ __align__(16) __half g_WiL[VOCAB*DHID];
__device__ __align__(16) __half g_ArH[NTOK*DHID];
__device__ __align__(16) __half g_ArL[NTOK*DHID];
__device__ __align__(16) __half g_AiH[NTOK*DHID];
__device__ __align__(16) __half g_AiL[NTOK*DHID];

// ---------------- small kernels ----------------
__global__ void embed_kernel(const int* __restrict__ ids, const float* __restrict__ emb) {
    int t = blockIdx.x, d = threadIdx.x;
    int id = ids[t];
    g_xr[t*DHID + d] = emb[(size_t)id*256 + d];
    g_xi[t*DHID + d] = emb[(size_t)id*256 + 128 + d];
}

__global__ void wsplit_kernel(const float* __restrict__ Wr, const float* __restrict__ Wi) {
    int i = blockIdx.x*256 + threadIdx.x;
    if (i < VOCAB*DHID) {
        float a = Wr[i];
        __half h = __float2half(a);
        g_WrH[i] = h; g_WrL[i] = __float2half(a - __half2float(h));
        float b = Wi[i];
        __half h2 = __float2half(b);
        g_WiH[i] = h2; g_WiL[i] = __float2half(b - __half2float(h2));
    }
}

__global__ void asplit_kernel() {
    int i = blockIdx.x*256 + threadIdx.x;
    float r = g_xr[i];
    __half h = __float2half(r);
    g_ArH[i] = h; g_ArL[i] = __float2half(r - __half2float(h));
    float q = g_xi[i];
    __half h2 = __float2half(q);
    g_AiH[i] = h2; g_AiL[i] = __float2half(q - __half2float(h2));
}

__global__ void xc_kernel(const float* __restrict__ cwl, const float* __restrict__ cbl) {
    __shared__ __align__(16) float xs[8*256];
    int tid = threadIdx.x, tBase = blockIdx.x*8;
    for (int i = tid; i < 8*256; i += 128) {
        int t = i >> 8, k = i & 255;
        xs[i] = (k < 128) ? g_xr[(tBase+t)*DHID + k] : g_xi[(tBase+t)*DHID + k - 128];
    }
    __syncthreads();
    int d = tid;
    float cb = cbl[d], acc[8];
    #pragma unroll
    for (int t = 0; t < 8; t++) acc[t] = cb;
    for (int k = 0; k < 256; k += 4) {
        float4 w = *reinterpret_cast<const float4*>(&cwl[d*256 + k]);
        #pragma unroll
        for (int t = 0; t < 8; t++) {
            acc[t] = fmaf(w.x, xs[t*256+k+0], acc[t]);
            acc[t] = fmaf(w.y, xs[t*256+k+1], acc[t]);
            acc[t] = fmaf(w.z, xs[t*256+k+2], acc[t]);
            acc[t] = fmaf(w.w, xs[t*256+k+3], acc[t]);
        }
    }
    #pragma unroll
    for (int t = 0; t < 8; t++) g_xc[(tBase+t)*DHID + d] = acc[t];
}

__global__ void theta_kernel(const float* __restrict__ Wl, const float* __restrict__ Bpl,
                             const float* __restrict__ acl, const float* __restrict__ asl) {
    __shared__ __align__(16) float xs[16*128];
    const float KSCALE = (float)(4096.0 / 6.283185307179586);
    const float ASTEP  = (float)(6.283185307179586 / 4096.0);
    const float PHI_F  = 1.6180339887498948f;
    int tid = threadIdx.x, warp = tid >> 5, lane = tid & 31;
    int n = blockIdx.x*4 + warp;
    int tBase = blockIdx.y*16;
    for (int i = tid; i < 16*128; i += 128)
        xs[i] = g_xc[(tBase + (i >> 7))*DHID + (i & 127)];
    __syncthreads();
    int d0 = lane*4;
    float4 w4  = *reinterpret_cast<const float4*>(&Wl [n*DHID + d0]);
    float4 bp4 = *reinterpret_cast<const float4*>(&Bpl[n*DHID + d0]);
    float4 ac4 = *reinterpret_cast<const float4*>(&acl[n*DHID + d0]);
    float4 as4 = *reinterpret_cast<const float4*>(&asl[n*DHID + d0]);
    float4 rw;
    rw.x = 1.0f/(1.0f+fabsf(w4.x)); rw.y = 1.0f/(1.0f+fabsf(w4.y));
    rw.z = 1.0f/(1.0f+fabsf(w4.z)); rw.w = 1.0f/(1.0f+fabsf(w4.w));
    for (int tt = 0; tt < 16; tt++) {
        int tok = tBase + tt;
        float tpos = (float)(tok & (SEQ-1)) * PHI_F;
        float4 x4 = *reinterpret_cast<const float4*>(&xs[tt*128 + d0]);
        float cs = 0.f, ss = 0.f, sv, cv, th; int idx;
        th = fmaf(x4.x, rw.x, bp4.x) + tpos;
        idx = __float2int_rd(th * KSCALE) & 4095;
        __sincosf((float)idx * ASTEP, &sv, &cv);
        cs = fmaf(cv, ac4.x, cs); ss = fmaf(sv, as4.x, ss);
        th = fmaf(x4.y, rw.y, bp4.y) + tpos;
        idx = __float2int_rd(th * KSCALE) & 4095;
        __sincosf((float)idx * ASTEP, &sv, &cv);
        cs = fmaf(cv, ac4.y, cs); ss = fmaf(sv, as4.y, ss);
        th = fmaf(x4.z, rw.z, bp4.z) + tpos;
        idx = __float2int_rd(th * KSCALE) & 4095;
        __sincosf((float)idx * ASTEP, &sv, &cv);
        cs = fmaf(cv, ac4.z, cs); ss = fmaf(sv, as4.z, ss);
        th = fmaf(x4.w, rw.w, bp4.w) + tpos;
        idx = __float2int_rd(th * KSCALE) & 4095;
        __sincosf((float)idx * ASTEP, &sv, &cv);
        cs = fmaf(cv, ac4.w, cs); ss = fmaf(sv, as4.w, ss);
        #pragma unroll
        for (int off = 16; off > 0; off >>= 1) {
            cs += __shfl_down_sync(0xffffffffu, cs, off);
            ss += __shfl_down_sync(0xffffffffu, ss, off);
        }
        if (lane == 0) { g_cs[tok*NFREQ + n] = cs; g_ss[tok*NFREQ + n] = ss; }
    }
}

__global__ void op_kernel(const float* __restrict__ oprl, const float* __restrict__ opil) {
    __shared__ __align__(16) float cs_s[8*256];
    __shared__ __align__(16) float ss_s[8*256];
    int tid = threadIdx.x, tBase = blockIdx.x*8;
    for (int i = tid; i < 8*256; i += 128) {
        int t = i >> 8, k = i & 255;
        cs_s[i] = g_cs[(tBase+t)*NFREQ + k];
        ss_s[i] = g_ss[(tBase+t)*NFREQ + k];
    }
    __syncthreads();
    int d = tid;
    float accr[8], acci[8];
    #pragma unroll
    for (int t = 0; t < 8; t++) { accr[t] = 0.f; acci[t] = 0.f; }
    for (int k = 0; k < 256; k += 4) {
        float4 wr = *reinterpret_cast<const float4*>(&oprl[d*256 + k]);
        float4 wi = *reinterpret_cast<const float4*>(&opil[d*256 + k]);
        #pragma unroll
        for (int t = 0; t < 8; t++) {
            accr[t] = fmaf(wr.x, cs_s[t*256+k+0], accr[t]);
            accr[t] = fmaf(wr.y, cs_s[t*256+k+1], accr[t]);
            accr[t] = fmaf(wr.z, cs_s[t*256+k+2], accr[t]);
            accr[t] = fmaf(wr.w, cs_s[t*256+k+3], accr[t]);
            acci[t] = fmaf(wi.x, ss_s[t*256+k+0], acci[t]);
            acci[t] = fmaf(wi.y, ss_s[t*256+k+1], acci[t]);
            acci[t] = fmaf(wi.z, ss_s[t*256+k+2], acci[t]);
            acci[t] = fmaf(wi.w, ss_s[t*256+k+3], acci[t]);
        }
    }
    #pragma unroll
    for (int t = 0; t < 8; t++) {
        float vr = accr[t], vi = acci[t];
        g_xr[(tBase+t)*DHID + d] = vr / (1.0f + expf(-vr));
        g_xi[(tBase+t)*DHID + d] = vi / (1.0f + expf(-vi));
    }
}

// ---------------- vocab GEMM: fp16x3 split, mma.sync, cp.async pipeline ----------------
// CTA tile: M=128 x N=32, K=128. 8 warps, 4m x 2n, warp tile 32x16 (mf=2, nf=2).
// A (4 split matrices) resident in smem per CTA; B double-buffered via cp.async.
#define ROWB   272              // smem row stride bytes (136 fp16) -> conflict-free
#define A_MTX  (128*ROWB)       // 34816
#define B_MTX  (32*ROWB)        // 8704
#define B_BUF  (4*B_MTX)        // 34816
#define SMEM_A (4*A_MTX)        // 139264
#define GEMM_SMEM (SMEM_A + 2*B_BUF)  // 208896
#define TILE_N   32
#define NT_TOT   1571           // ceil(50257/32)
#define CHUNKS   18
#define NT_CHUNK 88

__device__ __forceinline__ void mma_f16(float c[4], const uint32_t a[4], const uint32_t b[2]) {
    asm volatile(
        "mma.sync.aligned.m16n8k16.row.col.f32.f16.f16.f32 "
        "{%0,%1,%2,%3}, {%4,%5,%6,%7}, {%8,%9}, {%0,%1,%2,%3};\n"
        : "+f"(c[0]), "+f"(c[1]), "+f"(c[2]), "+f"(c[3])
        : "r"(a[0]), "r"(a[1]), "r"(a[2]), "r"(a[3]), "r"(b[0]), "r"(b[1]));
}
__device__ __forceinline__ void cp16(uint32_t dst, const void* src, int sz) {
    asm volatile("cp.async.cg.shared.global [%0], [%1], 16, %2;\n"
                 :: "r"(dst), "l"(src), "r"(sz));
}
__device__ __forceinline__ void cp_commit() { asm volatile("cp.async.commit_group;\n"); }
__device__ __forceinline__ void cp_wait0()  { asm volatile("cp.async.wait_group 0;\n"); }

__device__ __forceinline__ void prefetch_b(uint32_t dstBase, int nBase, int tid) {
    // 4 matrices x 32 rows x 16 chunks(16B) = 2048 chunks; 8 per thread
    #pragma unroll
    for (int j = 0; j < 8; j++) {
        int idx = tid + j*256;
        int mtx = idx >> 9;
        int rem = idx & 511;
        int r = rem >> 4, c = rem & 15;
        int v = nBase + r;
        int sz = (v < VOCAB) ? 16 : 0;
        int vc = (v < VOCAB) ? v : (VOCAB-1);
        const __half* s = (mtx == 0) ? g_WrH : (mtx == 1) ? g_WrL : (mtx == 2) ? g_WiH : g_WiL;
        cp16(dstBase + mtx*B_MTX + r*ROWB + c*16,
             (const char*)(s + (size_t)vc*DHID) + c*16, sz);
    }
}

__global__ void __launch_bounds__(256, 1) gemm_hmma(float* __restrict__ out) {
    extern __shared__ __align__(16) char sm[];
    uint32_t sbase;
    asm("{ .reg .u64 t; cvta.to.shared.u64 t, %1; cvt.u32.u64 %0, t; }" : "=r"(sbase) : "l"(sm));

    const int tid = threadIdx.x;
    const int mBase = blockIdx.y * 128;

    // ---- A: 4 split matrices, 128 rows x 256B, via cp.async (32 chunks/thread) ----
    #pragma unroll
    for (int j = 0; j < 32; j++) {
        int idx = tid + j*256;
        int mtx = idx >> 11;
        int rem = idx & 2047;
        int r = rem >> 4, c = rem & 15;
        const __half* s = (mtx == 0) ? g_ArH : (mtx == 1) ? g_ArL : (mtx == 2) ? g_AiH : g_AiL;
        cp16(sbase + mtx*A_MTX + r*ROWB + c*16,
             (const char*)(s + (size_t)(mBase + r)*DHID) + c*16, 16);
    }

    const int ntStart = blockIdx.x * NT_CHUNK;
    int ntEnd = ntStart + NT_CHUNK; if (ntEnd > NT_TOT) ntEnd = NT_TOT;
    const int T = ntEnd - ntStart;
    if (T <= 0) return;

    prefetch_b(sbase + SMEM_A, ntStart*TILE_N, tid);
    cp_commit();

    const int warp = tid >> 5, lane = tid & 31;
    const int wm = warp >> 1, wn = warp & 1;
    const int g = lane >> 2, tg = lane & 3;

    // per-thread base byte offsets
    const int aOff = (wm*32 + g)*ROWB + tg*4;   // + mf*16*ROWB, + kb, +16, +8*ROWB
    const int bOff = (wn*16 + g)*ROWB + tg*4;   // + nf*8*ROWB, + kb, +16

    for (int t = 0; t < T; t++) {
        const int cur = t & 1;
        const char* sB = sm + SMEM_A + cur*B_BUF;
        cp_wait0();
        __syncthreads();
        if (t + 1 < T) {
            prefetch_b(sbase + SMEM_A + (cur^1)*B_BUF, (ntStart + t + 1)*TILE_N, tid);
            cp_commit();
        }

        float acc[2][2][2][4];   // [lr/li][mf][nf][q]
        #pragma unroll
        for (int o = 0; o < 2; o++)
            #pragma unroll
            for (int mf = 0; mf < 2; mf++)
                #pragma unroll
                for (int nf = 0; nf < 2; nf++)
                    #pragma unroll
                    for (int q = 0; q < 4; q++) acc[o][mf][nf][q] = 0.f;

        #pragma unroll 1
        for (int ks = 0; ks < 8; ks++) {
            const int kb = ks*32;
            uint32_t A[4][2][4];   // [mtx: ArH ArL AiH AiL][mf][reg]
            #pragma unroll
            for (int mtx = 0; mtx < 4; mtx++)
                #pragma unroll
                for (int mf = 0; mf < 2; mf++) {
                    const char* p = sm + mtx*A_MTX + aOff + mf*(16*ROWB) + kb;
                    A[mtx][mf][0] = *(const uint32_t*)p;
                    A[mtx][mf][1] = *(const uint32_t*)(p + 8*ROWB);
                    A[mtx][mf][2] = *(const uint32_t*)(p + 16);
                    A[mtx][mf][3] = *(const uint32_t*)(p + 8*ROWB + 16);
                }
            uint32_t B[4][2][2];   // [mtx: WrH WrL WiH WiL][nf][reg]
            #pragma unroll
            for (int mtx = 0; mtx < 4; mtx++)
                #pragma unroll
                for (int nf = 0; nf < 2; nf++) {
                    const char* p = sB + mtx*B_MTX + bOff + nf*(8*ROWB) + kb;
                    B[mtx][nf][0] = *(const uint32_t*)p;
                    B[mtx][nf][1] = *(const uint32_t*)(p + 16);
                }
            // term-major issue: >=8 independent mmas between same-acc reuses
            #define MMTERM(o, am, bm) \
                { _Pragma("unroll") for (int mf = 0; mf < 2; mf++) \
                  _Pragma("unroll") for (int nf = 0; nf < 2; nf++) \
                      mma_f16(acc[o][mf][nf], A[am][mf], B[bm][nf]); }
            MMTERM(0, 0, 0)   // lr += ArH*WrH
            MMTERM(1, 2, 0)   // li += AiH*WrH
            MMTERM(0, 0, 1)   // lr += ArH*WrL
            MMTERM(1, 2, 1)   // li += AiH*WrL
            MMTERM(0, 1, 0)   // lr += ArL*WrH
            MMTERM(1, 3, 0)   // li += AiL*WrH
            MMTERM(1, 0, 2)   // li += ArH*WiH
            MMTERM(1, 0, 3)   // li += ArH*WiL
            MMTERM(1, 1, 2)   // li += ArL*WiH
            #pragma unroll
            for (int mf = 0; mf < 2; mf++)
                #pragma unroll
                for (int q = 0; q < 4; q++) {
                    A[2][mf][q] ^= 0x80008000u;   // -AiH
                    A[3][mf][q] ^= 0x80008000u;   // -AiL
                }
            MMTERM(0, 2, 2)   // lr -= AiH*WiH
            MMTERM(0, 2, 3)   // lr -= AiH*WiL
            MMTERM(0, 3, 2)   // lr -= AiL*WiH
            #undef MMTERM
        }

        // epilogue: out = sqrt(lr^2 + li^2 + 1e-8); scalar stores (VOCAB odd ->
        // row base can be 4B-aligned only; float2 would fault)
        const int nBase = (ntStart + t)*TILE_N;
        #pragma unroll
        for (int mf = 0; mf < 2; mf++) {
            const int row = mBase + wm*32 + mf*16 + g;
            #pragma unroll
            for (int nf = 0; nf < 2; nf++) {
                const int col = nBase + wn*16 + nf*8 + 2*tg;
                float* o0 = out + (size_t)row*VOCAB + col;
                float* o1 = o0 + (size_t)8*VOCAB;
                float lr0 = acc[0][mf][nf][0], li0 = acc[1][mf][nf][0];
                float lr1 = acc[0][mf][nf][1], li1 = acc[1][mf][nf][1];
                float lr2 = acc[0][mf][nf][2], li2 = acc[1][mf][nf][2];
                float lr3 = acc[0][mf][nf][3], li3 = acc[1][mf][nf][3];
                if (col < VOCAB) {
                    o0[0] = sqrtf(fmaf(lr0,lr0,fmaf(li0,li0,1e-8f)));
                    o1[0] = sqrtf(fmaf(lr2,lr2,fmaf(li2,li2,1e-8f)));
                }
                if (col + 1 < VOCAB) {
                    o0[1] = sqrtf(fmaf(lr1,lr1,fmaf(li1,li1,1e-8f)));
                    o1[1] = sqrtf(fmaf(lr3,lr3,fmaf(li3,li3,1e-8f)));
                }
            }
        }
        __syncthreads();
    }
}

// ---------------- launch ----------------
extern "C" void kernel_launch(void* const* d_in, const int* in_sizes, int n_in,
                              void* d_out, int out_size) {
    const int*   ids  = (const int*)  d_in[0];
    const float* emb  = (const float*)d_in[1];
    const float* cw   = (const float*)d_in[2];
    const float* cb   = (const float*)d_in[3];
    const float* W    = (const float*)d_in[4];
    const float* Bp   = (const float*)d_in[5];
    const float* acos_= (const float*)d_in[6];
    const float* asin_= (const float*)d_in[7];
    const float* opr  = (const float*)d_in[8];
    const float* opi  = (const float*)d_in[9];
    const float* Wr   = (const float*)d_in[10];
    const float* Wi   = (const float*)d_in[11];
    float* out = (float*)d_out;

    cudaFuncSetAttribute(gemm_hmma, cudaFuncAttributeMaxDynamicSharedMemorySize, GEMM_SMEM);

    embed_kernel<<<NTOK, 128>>>(ids, emb);
    wsplit_kernel<<<(VOCAB*DHID + 255)/256, 256>>>(Wr, Wi);

    for (int l = 0; l < 2; l++) {
        xc_kernel<<<NTOK/8, 128>>>(cw + (size_t)l*DHID*2*DHID, cb + (size_t)l*DHID);
        dim3 tg(NFREQ/4, NTOK/16);
        theta_kernel<<<tg, 128>>>(W + (size_t)l*NFREQ*DHID, Bp + (size_t)l*NFREQ*DHID,
                                  acos_ + (size_t)l*NFREQ*DHID, asin_ + (size_t)l*NFREQ*DHID);
        op_kernel<<<NTOK/8, 128>>>(opr + (size_t)l*DHID*NFREQ, opi + (size_t)l*DHID*NFREQ);
    }

    asplit_kernel<<<NTOK*DHID/256, 256>>>();
    gemm_hmma<<<dim3(CHUNKS, 8), 256, GEMM_SMEM>>>(out);
}

// round 6
// speedup vs baseline: 1.4544x; 1.0419x over previous
#include <cuda_runtime.h>
#include <cuda_fp16.h>
#include <math.h>
#include <stdint.h>

#define VOCAB 50257
#define DHID  128
#define NTOK  1024
#define NFREQ 256
#define SEQ   512

// ---------------- device scratch ----------------
__device__ __align__(16) float g_xr[NTOK*DHID];
__device__ __align__(16) float g_xi[NTOK*DHID];
__device__ __align__(16) float g_xc[NTOK*DHID];
__device__ __align__(16) float g_cs[NTOK*NFREQ];
__device__ __align__(16) float g_ss[NTOK*NFREQ];
__device__ __align__(16) __half g_WrH[VOCAB*DHID];
__device__ __align__(16) __half g_WrL[VOCAB*DHID];
__device__ __align__(16) __half g_WiH[VOCAB*DHID];
__device__ __align__(16) __half g_WiL[VOCAB*DHID];
__device__ __align__(16) __half g_ArH[NTOK*DHID];
__device__ __align__(16) __half g_ArL[NTOK*DHID];
__device__ __align__(16) __half g_AiH[NTOK*DHID];
__device__ __align__(16) __half g_AiL[NTOK*DHID];

// ---------------- small kernels ----------------
__global__ void embed_kernel(const int* __restrict__ ids, const float* __restrict__ emb) {
    int t = blockIdx.x, d = threadIdx.x;
    int id = ids[t];
    g_xr[t*DHID + d] = emb[(size_t)id*256 + d];
    g_xi[t*DHID + d] = emb[(size_t)id*256 + 128 + d];
}

__global__ void wsplit_kernel(const float* __restrict__ Wr, const float* __restrict__ Wi) {
    int i = blockIdx.x*256 + threadIdx.x;
    if (i < VOCAB*DHID) {
        float a = Wr[i];
        __half h = __float2half(a);
        g_WrH[i] = h; g_WrL[i] = __float2half(a - __half2float(h));
        float b = Wi[i];
        __half h2 = __float2half(b);
        g_WiH[i] = h2; g_WiL[i] = __float2half(b - __half2float(h2));
    }
}

__global__ void asplit_kernel() {
    int i = blockIdx.x*256 + threadIdx.x;
    float r = g_xr[i];
    __half h = __float2half(r);
    g_ArH[i] = h; g_ArL[i] = __float2half(r - __half2float(h));
    float q = g_xi[i];
    __half h2 = __float2half(q);
    g_AiH[i] = h2; g_AiL[i] = __float2half(q - __half2float(h2));
}

__global__ void xc_kernel(const float* __restrict__ cwl, const float* __restrict__ cbl) {
    __shared__ __align__(16) float xs[8*256];
    int tid = threadIdx.x, tBase = blockIdx.x*8;
    for (int i = tid; i < 8*256; i += 128) {
        int t = i >> 8, k = i & 255;
        xs[i] = (k < 128) ? g_xr[(tBase+t)*DHID + k] : g_xi[(tBase+t)*DHID + k - 128];
    }
    __syncthreads();
    int d = tid;
    float cb = cbl[d], acc[8];
    #pragma unroll
    for (int t = 0; t < 8; t++) acc[t] = cb;
    for (int k = 0; k < 256; k += 4) {
        float4 w = *reinterpret_cast<const float4*>(&cwl[d*256 + k]);
        #pragma unroll
        for (int t = 0; t < 8; t++) {
            acc[t] = fmaf(w.x, xs[t*256+k+0], acc[t]);
            acc[t] = fmaf(w.y, xs[t*256+k+1], acc[t]);
            acc[t] = fmaf(w.z, xs[t*256+k+2], acc[t]);
            acc[t] = fmaf(w.w, xs[t*256+k+3], acc[t]);
        }
    }
    #pragma unroll
    for (int t = 0; t < 8; t++) g_xc[(tBase+t)*DHID + d] = acc[t];
}

__global__ void theta_kernel(const float* __restrict__ Wl, const float* __restrict__ Bpl,
                             const float* __restrict__ acl, const float* __restrict__ asl) {
    __shared__ __align__(16) float xs[16*128];
    const float KSCALE = (float)(4096.0 / 6.283185307179586);
    const float ASTEP  = (float)(6.283185307179586 / 4096.0);
    const float PHI_F  = 1.6180339887498948f;
    int tid = threadIdx.x, warp = tid >> 5, lane = tid & 31;
    int n = blockIdx.x*4 + warp;
    int tBase = blockIdx.y*16;
    for (int i = tid; i < 16*128; i += 128)
        xs[i] = g_xc[(tBase + (i >> 7))*DHID + (i & 127)];
    __syncthreads();
    int d0 = lane*4;
    float4 w4  = *reinterpret_cast<const float4*>(&Wl [n*DHID + d0]);
    float4 bp4 = *reinterpret_cast<const float4*>(&Bpl[n*DHID + d0]);
    float4 ac4 = *reinterpret_cast<const float4*>(&acl[n*DHID + d0]);
    float4 as4 = *reinterpret_cast<const float4*>(&asl[n*DHID + d0]);
    float4 rw;
    rw.x = 1.0f/(1.0f+fabsf(w4.x)); rw.y = 1.0f/(1.0f+fabsf(w4.y));
    rw.z = 1.0f/(1.0f+fabsf(w4.z)); rw.w = 1.0f/(1.0f+fabsf(w4.w));
    for (int tt = 0; tt < 16; tt++) {
        int tok = tBase + tt;
        float tpos = (float)(tok & (SEQ-1)) * PHI_F;
        float4 x4 = *reinterpret_cast<const float4*>(&xs[tt*128 + d0]);
        float cs = 0.f, ss = 0.f, sv, cv, th; int idx;
        th = fmaf(x4.x, rw.x, bp4.x) + tpos;
        idx = __float2int_rd(th * KSCALE) & 4095;
        __sincosf((float)idx * ASTEP, &sv, &cv);
        cs = fmaf(cv, ac4.x, cs); ss = fmaf(sv, as4.x, ss);
        th = fmaf(x4.y, rw.y, bp4.y) + tpos;
        idx = __float2int_rd(th * KSCALE) & 4095;
        __sincosf((float)idx * ASTEP, &sv, &cv);
        cs = fmaf(cv, ac4.y, cs); ss = fmaf(sv, as4.y, ss);
        th = fmaf(x4.z, rw.z, bp4.z) + tpos;
        idx = __float2int_rd(th * KSCALE) & 4095;
        __sincosf((float)idx * ASTEP, &sv, &cv);
        cs = fmaf(cv, ac4.z, cs); ss = fmaf(sv, as4.z, ss);
        th = fmaf(x4.w, rw.w, bp4.w) + tpos;
        idx = __float2int_rd(th * KSCALE) & 4095;
        __sincosf((float)idx * ASTEP, &sv, &cv);
        cs = fmaf(cv, ac4.w, cs); ss = fmaf(sv, as4.w, ss);
        #pragma unroll
        for (int off = 16; off > 0; off >>= 1) {
            cs += __shfl_down_sync(0xffffffffu, cs, off);
            ss += __shfl_down_sync(0xffffffffu, ss, off);
        }
        if (lane == 0) { g_cs[tok*NFREQ + n] = cs; g_ss[tok*NFREQ + n] = ss; }
    }
}

__global__ void op_kernel(const float* __restrict__ oprl, const float* __restrict__ opil) {
    __shared__ __align__(16) float cs_s[8*256];
    __shared__ __align__(16) float ss_s[8*256];
    int tid = threadIdx.x, tBase = blockIdx.x*8;
    for (int i = tid; i < 8*256; i += 128) {
        int t = i >> 8, k = i & 255;
        cs_s[i] = g_cs[(tBase+t)*NFREQ + k];
        ss_s[i] = g_ss[(tBase+t)*NFREQ + k];
    }
    __syncthreads();
    int d = tid;
    float accr[8], acci[8];
    #pragma unroll
    for (int t = 0; t < 8; t++) { accr[t] = 0.f; acci[t] = 0.f; }
    for (int k = 0; k < 256; k += 4) {
        float4 wr = *reinterpret_cast<const float4*>(&oprl[d*256 + k]);
        float4 wi = *reinterpret_cast<const float4*>(&opil[d*256 + k]);
        #pragma unroll
        for (int t = 0; t < 8; t++) {
            accr[t] = fmaf(wr.x, cs_s[t*256+k+0], accr[t]);
            accr[t] = fmaf(wr.y, cs_s[t*256+k+1], accr[t]);
            accr[t] = fmaf(wr.z, cs_s[t*256+k+2], accr[t]);
            accr[t] = fmaf(wr.w, cs_s[t*256+k+3], accr[t]);
            acci[t] = fmaf(wi.x, ss_s[t*256+k+0], acci[t]);
            acci[t] = fmaf(wi.y, ss_s[t*256+k+1], acci[t]);
            acci[t] = fmaf(wi.z, ss_s[t*256+k+2], acci[t]);
            acci[t] = fmaf(wi.w, ss_s[t*256+k+3], acci[t]);
        }
    }
    #pragma unroll
    for (int t = 0; t < 8; t++) {
        float vr = accr[t], vi = acci[t];
        g_xr[(tBase+t)*DHID + d] = vr / (1.0f + expf(-vr));
        g_xi[(tBase+t)*DHID + d] = vi / (1.0f + expf(-vi));
    }
}

// ---------------- vocab GEMM: fp16x3 split, mma.sync + ldmatrix, cp.async ----------------
#define ROWB   272
#define A_MTX  (128*ROWB)
#define B_MTX  (32*ROWB)
#define B_BUF  (4*B_MTX)
#define SMEM_A (4*A_MTX)
#define GEMM_SMEM (SMEM_A + 2*B_BUF)
#define TILE_N   32
#define NT_TOT   1571
#define CHUNKS   18
#define NT_CHUNK 88

__device__ __forceinline__ void mma_f16(float c[4], const uint32_t a[4], const uint32_t b[2]) {
    asm volatile(
        "mma.sync.aligned.m16n8k16.row.col.f32.f16.f16.f32 "
        "{%0,%1,%2,%3}, {%4,%5,%6,%7}, {%8,%9}, {%0,%1,%2,%3};\n"
        : "+f"(c[0]), "+f"(c[1]), "+f"(c[2]), "+f"(c[3])
        : "r"(a[0]), "r"(a[1]), "r"(a[2]), "r"(a[3]), "r"(b[0]), "r"(b[1]));
}
__device__ __forceinline__ void ldsm_x4(uint32_t r[4], uint32_t addr) {
    asm volatile("ldmatrix.sync.aligned.m8n8.x4.shared.b16 {%0,%1,%2,%3}, [%4];\n"
                 : "=r"(r[0]), "=r"(r[1]), "=r"(r[2]), "=r"(r[3]) : "r"(addr));
}
__device__ __forceinline__ void cp16(uint32_t dst, const void* src, int sz) {
    asm volatile("cp.async.cg.shared.global [%0], [%1], 16, %2;\n"
                 :: "r"(dst), "l"(src), "r"(sz));
}
__device__ __forceinline__ void cp_commit() { asm volatile("cp.async.commit_group;\n"); }
__device__ __forceinline__ void cp_wait0()  { asm volatile("cp.async.wait_group 0;\n"); }

__device__ __forceinline__ void prefetch_b(uint32_t dstBase, int nBase, int tid) {
    #pragma unroll
    for (int j = 0; j < 8; j++) {
        int idx = tid + j*256;
        int mtx = idx >> 9;
        int rem = idx & 511;
        int r = rem >> 4, c = rem & 15;
        int v = nBase + r;
        int sz = (v < VOCAB) ? 16 : 0;
        int vc = (v < VOCAB) ? v : (VOCAB-1);
        const __half* s = (mtx == 0) ? g_WrH : (mtx == 1) ? g_WrL : (mtx == 2) ? g_WiH : g_WiL;
        cp16(dstBase + mtx*B_MTX + r*ROWB + c*16,
             (const char*)(s + (size_t)vc*DHID) + c*16, sz);
    }
}

__global__ void __launch_bounds__(256, 1) gemm_hmma(float* __restrict__ out) {
    extern __shared__ __align__(16) char sm[];
    uint32_t sbase;
    asm("{ .reg .u64 t; cvta.to.shared.u64 t, %1; cvt.u32.u64 %0, t; }" : "=r"(sbase) : "l"(sm));

    const int tid = threadIdx.x;
    const int mBase = blockIdx.y * 128;

    // ---- A: 4 split matrices via cp.async ----
    #pragma unroll
    for (int j = 0; j < 32; j++) {
        int idx = tid + j*256;
        int mtx = idx >> 11;
        int rem = idx & 2047;
        int r = rem >> 4, c = rem & 15;
        const __half* s = (mtx == 0) ? g_ArH : (mtx == 1) ? g_ArL : (mtx == 2) ? g_AiH : g_AiL;
        cp16(sbase + mtx*A_MTX + r*ROWB + c*16,
             (const char*)(s + (size_t)(mBase + r)*DHID) + c*16, 16);
    }

    const int ntStart = blockIdx.x * NT_CHUNK;
    int ntEnd = ntStart + NT_CHUNK; if (ntEnd > NT_TOT) ntEnd = NT_TOT;
    const int T = ntEnd - ntStart;
    if (T <= 0) return;

    prefetch_b(sbase + SMEM_A, ntStart*TILE_N, tid);
    cp_commit();

    const int warp = tid >> 5, lane = tid & 31;
    const int wm = warp >> 1, wn = warp & 1;
    const int g = lane >> 2, tg = lane & 3;

    // ---- ldmatrix lane-address bases ----
    // A x4 (per mtx, per mf): row = wm*32 + mf*16 + (l&7) + (l&8); col16 = (l&16)?16:0
    uint32_t aB[4][2];
    {
        const int arow = (lane & 7) + (lane & 8);
        const int acol = (lane & 16) ? 16 : 0;
        #pragma unroll
        for (int mtx = 0; mtx < 4; mtx++)
            #pragma unroll
            for (int mf = 0; mf < 2; mf++)
                aB[mtx][mf] = sbase + mtx*A_MTX + (wm*32 + mf*16 + arow)*ROWB + acol;
    }
    // B x4 (per mtx): row = wn*16 + (l&7) + ((l&16)?8:0); col16 = (l&8)?16:0
    // -> regs {nf0.b0, nf0.b1, nf1.b0, nf1.b1}
    uint32_t bB[4];
    {
        const int brow = (lane & 7) + ((lane & 16) ? 8 : 0);
        const int bcol = (lane & 8) ? 16 : 0;
        #pragma unroll
        for (int mtx = 0; mtx < 4; mtx++)
            bB[mtx] = sbase + SMEM_A + mtx*B_MTX + (wn*16 + brow)*ROWB + bcol;
    }

    for (int t = 0; t < T; t++) {
        const int cur = t & 1;
        const uint32_t bOffBuf = (uint32_t)cur*B_BUF;
        cp_wait0();
        __syncthreads();
        if (t + 1 < T) {
            prefetch_b(sbase + SMEM_A + (cur^1)*B_BUF, (ntStart + t + 1)*TILE_N, tid);
            cp_commit();
        }

        float acc[2][2][2][4];   // [lr/li][mf][nf][q]
        #pragma unroll
        for (int o = 0; o < 2; o++)
            #pragma unroll
            for (int mf = 0; mf < 2; mf++)
                #pragma unroll
                for (int nf = 0; nf < 2; nf++)
                    #pragma unroll
                    for (int q = 0; q < 4; q++) acc[o][mf][nf][q] = 0.f;

        #pragma unroll 2
        for (int ks = 0; ks < 8; ks++) {
            const uint32_t kb = ks*32;
            uint32_t A[4][2][4];   // [ArH ArL AiH AiL][mf][reg]
            #pragma unroll
            for (int mtx = 0; mtx < 4; mtx++)
                #pragma unroll
                for (int mf = 0; mf < 2; mf++)
                    ldsm_x4(A[mtx][mf], aB[mtx][mf] + kb);
            uint32_t Bf[4][4];     // [WrH WrL WiH WiL][{nf0b0,nf0b1,nf1b0,nf1b1}]
            #pragma unroll
            for (int mtx = 0; mtx < 4; mtx++)
                ldsm_x4(Bf[mtx], bB[mtx] + bOffBuf + kb);

            #define MMTERM(o, am, bm) \
                { _Pragma("unroll") for (int mf = 0; mf < 2; mf++) \
                  _Pragma("unroll") for (int nf = 0; nf < 2; nf++) \
                      mma_f16(acc[o][mf][nf], A[am][mf], &Bf[bm][nf*2]); }
            MMTERM(0, 0, 0)   // lr += ArH*WrH
            MMTERM(1, 2, 0)   // li += AiH*WrH
            MMTERM(0, 0, 1)   // lr += ArH*WrL
            MMTERM(1, 2, 1)   // li += AiH*WrL
            MMTERM(0, 1, 0)   // lr += ArL*WrH
            MMTERM(1, 3, 0)   // li += AiL*WrH
            MMTERM(1, 0, 2)   // li += ArH*WiH
            MMTERM(1, 0, 3)   // li += ArH*WiL
            MMTERM(1, 1, 2)   // li += ArL*WiH
            #pragma unroll
            for (int mf = 0; mf < 2; mf++)
                #pragma unroll
                for (int q = 0; q < 4; q++) {
                    A[2][mf][q] ^= 0x80008000u;   // -AiH
                    A[3][mf][q] ^= 0x80008000u;   // -AiL
                }
            MMTERM(0, 2, 2)   // lr -= AiH*WiH
            MMTERM(0, 2, 3)   // lr -= AiH*WiL
            MMTERM(0, 3, 2)   // lr -= AiL*WiH
            #undef MMTERM
        }

        // epilogue (scalar stores: VOCAB odd -> only 4B alignment guaranteed)
        const int nBase = (ntStart + t)*TILE_N;
        #pragma unroll
        for (int mf = 0; mf < 2; mf++) {
            const int row = mBase + wm*32 + mf*16 + g;
            #pragma unroll
            for (int nf = 0; nf < 2; nf++) {
                const int col = nBase + wn*16 + nf*8 + 2*tg;
                float* o0 = out + (size_t)row*VOCAB + col;
                float* o1 = o0 + (size_t)8*VOCAB;
                float lr0 = acc[0][mf][nf][0], li0 = acc[1][mf][nf][0];
                float lr1 = acc[0][mf][nf][1], li1 = acc[1][mf][nf][1];
                float lr2 = acc[0][mf][nf][2], li2 = acc[1][mf][nf][2];
                float lr3 = acc[0][mf][nf][3], li3 = acc[1][mf][nf][3];
                if (col < VOCAB) {
                    o0[0] = sqrtf(fmaf(lr0,lr0,fmaf(li0,li0,1e-8f)));
                    o1[0] = sqrtf(fmaf(lr2,lr2,fmaf(li2,li2,1e-8f)));
                }
                if (col + 1 < VOCAB) {
                    o0[1] = sqrtf(fmaf(lr1,lr1,fmaf(li1,li1,1e-8f)));
                    o1[1] = sqrtf(fmaf(lr3,lr3,fmaf(li3,li3,1e-8f)));
                }
            }
        }
        __syncthreads();
    }
}

// ---------------- launch ----------------
extern "C" void kernel_launch(void* const* d_in, const int* in_sizes, int n_in,
                              void* d_out, int out_size) {
    const int*   ids  = (const int*)  d_in[0];
    const float* emb  = (const float*)d_in[1];
    const float* cw   = (const float*)d_in[2];
    const float* cb   = (const float*)d_in[3];
    const float* W    = (const float*)d_in[4];
    const float* Bp   = (const float*)d_in[5];
    const float* acos_= (const float*)d_in[6];
    const float* asin_= (const float*)d_in[7];
    const float* opr  = (const float*)d_in[8];
    const float* opi  = (const float*)d_in[9];
    const float* Wr   = (const float*)d_in[10];
    const float* Wi   = (const float*)d_in[11];
    float* out = (float*)d_out;

    cudaFuncSetAttribute(gemm_hmma, cudaFuncAttributeMaxDynamicSharedMemorySize, GEMM_SMEM);

    embed_kernel<<<NTOK, 128>>>(ids, emb);
    wsplit_kernel<<<(VOCAB*DHID + 255)/256, 256>>>(Wr, Wi);

    for (int l = 0; l < 2; l++) {
        xc_kernel<<<NTOK/8, 128>>>(cw + (size_t)l*DHID*2*DHID, cb + (size_t)l*DHID);
        dim3 tg(NFREQ/4, NTOK/16);
        theta_kernel<<<tg, 128>>>(W + (size_t)l*NFREQ*DHID, Bp + (size_t)l*NFREQ*DHID,
                                  acos_ + (size_t)l*NFREQ*DHID, asin_ + (size_t)l*NFREQ*DHID);
        op_kernel<<<NTOK/8, 128>>>(opr + (size_t)l*DHID*NFREQ, opi + (size_t)l*DHID*NFREQ);
    }

    asplit_kernel<<<NTOK*DHID/256, 256>>>();
    gemm_hmma<<<dim3(CHUNKS, 8), 256, GEMM_SMEM>>>(out);
}